// round 15
// baseline (speedup 1.0000x reference)
#include <cuda_runtime.h>
#include <cuda_fp16.h>
#include <cstdint>

#define Bn 64
#define Nn 50000
#define Ln 8
#define En 100000
#define Un 20000
#define Gn 20000
#define Rn 64
#define Dn 16
#define Cn 2
#define ND (Bn*Dn)     /* 1024 elements per row */
#define NBLK 1024      /* k_layer grid.x */

// Scratch (device globals; zero at module load).
__device__ __half g_h[(size_t)Nn * ND];        // ~102 MB initial node values
__device__ __half g_v[(size_t)Ln * Un * ND];   // ~328 MB version rows [l][u][b][d]
__device__ int    g_csr[Ln * En];              // edge ids after fill; row ids after k_finish
__device__ int    g_off[Ln * (Un + 1)];
__device__ int    g_len[Ln * Un];
__device__ int    g_cnt[Ln * Un];
__device__ int    g_cur[Ln * Un];
__device__ int    g_first[Nn];
__device__ int    g_mask[Nn];
__device__ int    g_inv[Ln * Nn];
__device__ int    g_need[Ln * Un];
__device__ int    g_list[Ln * Un];
__device__ int    g_ncnt[Ln];
__device__ int    g_rootrow[Rn];

// Manual grid barrier (k_live only; all blocks co-resident via launch_bounds(128,8)).
__device__ volatile unsigned g_gen = 0;
__device__ unsigned g_barcnt = 0;

__device__ __forceinline__ void gsync(int nb) {
    __threadfence();
    __syncthreads();
    if (threadIdx.x == 0) {
        unsigned gen = g_gen;
        unsigned a = atomicAdd(&g_barcnt, 1u);
        if (a == (unsigned)nb - 1u) {
            g_barcnt = 0;
            __threadfence();
            g_gen = gen + 1u;
        } else {
            while (g_gen == gen) { __nanosleep(32); }
        }
    }
    __syncthreads();
}

__global__ void k_zero_int() {
    int i = blockIdx.x * blockDim.x + threadIdx.x;
    if (i < Ln * Un) { g_cnt[i] = 0; g_cur[i] = 0; g_need[i] = 0; }
    if (i < Nn) { g_first[i] = 127; g_mask[i] = 0; }
}

__global__ void k_alive(const int* __restrict__ gene_map, const int* __restrict__ dst_unique) {
    int i = blockIdx.x * blockDim.x + threadIdx.x;
    if (i < Gn) {
        atomicMin(&g_first[gene_map[i]], -1);
    } else if (i < Gn + Ln * Un) {
        int k = i - Gn;
        int l = k / Un;
        int u = k - l * Un;
        int node = dst_unique[k];
        atomicMin(&g_first[node], l);
        atomicOr(&g_mask[node], 1 << l);
        g_inv[l * Nn + node] = u;
    }
}

__global__ void k_gene(const float* __restrict__ X, const float* __restrict__ w_in,
                       const float* __restrict__ b_in, const int* __restrict__ gene_map) {
    int g = blockIdx.x;
    int t = threadIdx.x;
    int b = t >> 2, j0 = (t & 3) << 2;
    int node = gene_map[g];
    float x = X[(size_t)b * Gn + g];
    float4 w  = *(const float4*)(w_in + j0);
    float4 bi = *(const float4*)(b_in + j0);
    __half2 h01 = __floats2half2_rn(fmaf(x, w.x, bi.x), fmaf(x, w.y, bi.y));
    __half2 h23 = __floats2half2_rn(fmaf(x, w.z, bi.z), fmaf(x, w.w, bi.w));
    __half2* dst = (__half2*)(g_h + (size_t)node * ND + t * 4);
    dst[0] = h01;
    dst[1] = h23;
}

__global__ void k_hist(const int* __restrict__ dst_pos) {
    int i = blockIdx.x * blockDim.x + threadIdx.x;
    if (i < Ln * En) {
        int l = i / En;
        atomicAdd(&g_cnt[l * Un + dst_pos[i]], 1);
    }
}

__global__ void k_scan() {
    int l = blockIdx.x;
    const int* c = g_cnt + l * Un;
    int* o = g_off + l * (Un + 1);
    int t = threadIdx.x;
    int lane = t & 31, wid = t >> 5;
    int base = t * 20;
    int cnt[20];
    int s = 0;
    #pragma unroll
    for (int i = 0; i < 20; i++) {
        int idx = base + i;
        cnt[i] = (idx < Un) ? c[idx] : 0;
        s += cnt[i];
    }
    int v = s;
    #pragma unroll
    for (int d = 1; d < 32; d <<= 1) {
        int w = __shfl_up_sync(0xffffffffu, v, d);
        if (lane >= d) v += w;
    }
    __shared__ int wsum[32];
    if (lane == 31) wsum[wid] = v;
    __syncthreads();
    if (wid == 0) {
        int wv = wsum[lane];
        #pragma unroll
        for (int d = 1; d < 32; d <<= 1) {
            int w = __shfl_up_sync(0xffffffffu, wv, d);
            if (lane >= d) wv += w;
        }
        wsum[lane] = wv;
    }
    __syncthreads();
    int run = v - s + (wid > 0 ? wsum[wid - 1] : 0);
    #pragma unroll
    for (int i = 0; i < 20; i++) {
        int idx = base + i;
        if (idx < Un) {
            o[idx] = run;
            run += cnt[i];
        }
    }
    if (t == 1023) o[Un] = run;
}

__global__ void k_fill(const int* __restrict__ dst_pos) {
    int i = blockIdx.x * blockDim.x + threadIdx.x;
    if (i < Ln * En) {
        int l = i / En;
        int e = i - l * En;
        int u = dst_pos[i];
        int slot = g_off[l * (Un + 1) + u] + atomicAdd(&g_cur[l * Un + u], 1);
        g_csr[l * En + slot] = e;
    }
}

// Persistent liveness kernel: seed | back x8 | compact. Tiny balanced work -> safe to fuse.
__global__ __launch_bounds__(128, 8) void k_live(const int* __restrict__ roots,
                                                 const int* __restrict__ src) {
    int nb = gridDim.x, bid = blockIdx.x, t = threadIdx.x;
    int gs = nb * 128, gt = bid * 128 + t;

    if (bid == 0) {
        if (t < Ln) g_ncnt[t] = 0;
        if (t < Rn) {
            int node = roots[t];
            int m = g_mask[node];
            if (m) {
                int k = 31 - __clz((unsigned)m);
                int u = g_inv[k * Nn + node];
                g_need[k * Un + u] = 1;
                g_rootrow[t] = Nn + k * Un + u;
            } else {
                g_rootrow[t] = node;
            }
        }
    }
    gsync(nb);

    // Backward liveness over RAW edge ids (resolve src on the fly).
    for (int l = Ln - 1; l >= 0; l--) {
        const int* sl = src + l * En;
        unsigned below = (1u << l) - 1u;
        for (int u = gt; u < Un; u += gs) {
            if (g_need[l * Un + u]) {
                int lo = g_off[l * (Un + 1) + u];
                int hi = g_off[l * (Un + 1) + u + 1];
                const int* e = g_csr + l * En;
                for (int i = lo; i < hi; i++) {
                    int s = sl[e[i]];
                    if (g_first[s] < l) {
                        unsigned m = (unsigned)g_mask[s] & below;
                        if (m) {
                            int k = 31 - __clz(m);
                            g_need[k * Un + g_inv[k * Nn + s]] = 1;
                        }
                    }
                }
            }
        }
        gsync(nb);
    }

    // Compact (list order irrelevant: slots independent, per-slot sum order fixed later).
    for (int i = gt; i < Ln * Un; i += gs) {
        if (g_need[i]) {
            int l = i / Un;
            int pos = atomicAdd(&g_ncnt[l], 1);
            g_list[l * Un + pos] = i - l * Un;
        }
    }
}

// For NEEDED buckets only: sort edge ids (deterministic sum order), map to absolute
// row ids, compact to alive srcs. ~18% of buckets -> ~5x cheaper than sorting all.
__global__ void k_finish(const int* __restrict__ src) {
    int gid = blockIdx.x * blockDim.x + threadIdx.x;
    if (gid >= Ln * Un) return;
    if (!g_need[gid]) return;
    int l = gid / Un;
    int u = gid - l * Un;
    int* seg = g_csr + l * En;
    int lo = g_off[l * (Un + 1) + u];
    int hi = g_off[l * (Un + 1) + u + 1];
    for (int i = lo + 1; i < hi; i++) {
        int key = seg[i];
        int j = i - 1;
        while (j >= lo && seg[j] > key) { seg[j + 1] = seg[j]; j--; }
        seg[j + 1] = key;
    }
    const int* sl = src + l * En;
    unsigned below = (1u << l) - 1u;
    int w = lo;
    for (int i = lo; i < hi; i++) {
        int s = sl[seg[i]];
        if (g_first[s] < l) {
            unsigned m = (unsigned)g_mask[s] & below;
            int row;
            if (m) {
                int k = 31 - __clz(m);
                row = Nn + k * Un + g_inv[k * Nn + s];
            } else {
                row = s;
            }
            seg[w++] = row;
        }
    }
    g_len[l * Un + u] = w - lo;
}

// Fused layer kernel (round-13 structure, unchanged hot loop).
__global__ __launch_bounds__(128) void k_layer(int l, const float* __restrict__ W,
                                               const float* __restrict__ bias,
                                               const int* __restrict__ dstu) {
    __shared__ float sW[256];
    __shared__ int scnt;
    int t = threadIdx.x;
    if (t == 0) scnt = g_ncnt[l];
    const float* Wl = W + l * Dn * Dn;
    sW[t] = Wl[t];
    sW[t + 128] = Wl[t + 128];
    __syncthreads();
    int cnt = scnt;

    int half = t >> 6;
    int tt = t & 63;
    int kh = tt & 1;
    int k0 = kh << 3;
    size_t col = ((size_t)blockIdx.y << 9) + ((size_t)tt << 3);
    const unsigned long long* sW64 = (const unsigned long long*)sW;

    for (int it = blockIdx.x * 2 + half; it < cnt; it += NBLK * 2) {
        int u = g_list[l * Un + it];
        int lo = g_off[l * (Un + 1) + u];
        int n = g_len[l * Un + u];
        const int* e = g_csr + l * En + lo;

        float a[8] = {0.f, 0.f, 0.f, 0.f, 0.f, 0.f, 0.f, 0.f};
        uint4 p0, p1;
        if (n > 0) {
            int r = e[0];
            const __half* bp = (r < Nn) ? (g_h + (size_t)r * ND) : (g_v + (size_t)(r - Nn) * ND);
            p0 = *(const uint4*)(bp + col);
        }
        if (n > 1) {
            int r = e[1];
            const __half* bp = (r < Nn) ? (g_h + (size_t)r * ND) : (g_v + (size_t)(r - Nn) * ND);
            p1 = *(const uint4*)(bp + col);
        }
        for (int i = 0; i < n; i++) {
            uint4 d = p0;
            p0 = p1;
            if (i + 2 < n) {
                int r = e[i + 2];
                const __half* bp = (r < Nn) ? (g_h + (size_t)r * ND) : (g_v + (size_t)(r - Nn) * ND);
                p1 = *(const uint4*)(bp + col);
            }
            float2 f0 = __half22float2(*(const __half2*)&d.x);
            float2 f1 = __half22float2(*(const __half2*)&d.y);
            float2 f2 = __half22float2(*(const __half2*)&d.z);
            float2 f3 = __half22float2(*(const __half2*)&d.w);
            a[0] += f0.x; a[1] += f0.y; a[2] += f1.x; a[3] += f1.y;
            a[4] += f2.x; a[5] += f2.y; a[6] += f3.x; a[7] += f3.y;
        }

        unsigned long long acc[8];
        #pragma unroll
        for (int jp = 0; jp < 8; jp++) acc[jp] = 0ull;
        #pragma unroll
        for (int kk = 0; kk < 8; kk++) {
            unsigned long long s2;
            asm("mov.b64 %0, {%1, %1};" : "=l"(s2) : "f"(a[kk]));
            int rb = (k0 + kk) << 3;
            #pragma unroll
            for (int jp = 0; jp < 8; jp++) {
                asm("fma.rn.f32x2 %0, %1, %2, %0;" : "+l"(acc[jp]) : "l"(s2), "l"(sW64[rb + jp]));
            }
        }

        int mb = kh << 2, ob = (kh ^ 1) << 2;
        float r[8];
        #pragma unroll
        for (int i = 0; i < 4; i++) {
            unsigned long long mine  = acc[mb + i];
            unsigned long long other = __shfl_xor_sync(0xffffffffu, acc[ob + i], 1);
            float mlo, mhi, olo, ohi;
            asm("mov.b64 {%0, %1}, %2;" : "=f"(mlo), "=f"(mhi) : "l"(mine));
            asm("mov.b64 {%0, %1}, %2;" : "=f"(olo), "=f"(ohi) : "l"(other));
            r[i * 2]     = mlo + olo;
            r[i * 2 + 1] = mhi + ohi;
        }

        int node = dstu[u];
        float4 b0 = *(const float4*)(bias + (size_t)node * Dn + k0);
        float4 b1 = *(const float4*)(bias + (size_t)node * Dn + k0 + 4);
        __half2 o0 = __floats2half2_rn(tanhf(r[0] + b0.x), tanhf(r[1] + b0.y));
        __half2 o1 = __floats2half2_rn(tanhf(r[2] + b0.z), tanhf(r[3] + b0.w));
        __half2 o2 = __floats2half2_rn(tanhf(r[4] + b1.x), tanhf(r[5] + b1.y));
        __half2 o3 = __floats2half2_rn(tanhf(r[6] + b1.z), tanhf(r[7] + b1.w));
        __half2* dst = (__half2*)(g_v + ((size_t)(l * Un + u)) * ND + col);
        dst[0] = o0; dst[1] = o1; dst[2] = o2; dst[3] = o3;
    }
}

__global__ void k_head(const float* __restrict__ Wh, const float* __restrict__ bh,
                       float* __restrict__ out) {
    int b = blockIdx.x;
    int t = threadIdx.x;
    float a0 = 0.f, a1 = 0.f;
    for (int i = t; i < Rn * Dn; i += 256) {
        int r = i >> 4, j = i & 15;
        int row = g_rootrow[r];
        const __half* bp = (row < Nn) ? (g_h + (size_t)row * ND) : (g_v + (size_t)(row - Nn) * ND);
        float f = __half2float(bp[(b << 4) + j]);
        a0 = fmaf(f, Wh[i], a0);
        a1 = fmaf(f, Wh[Rn * Dn + i], a1);
    }
    __shared__ float s0[256], s1[256];
    s0[t] = a0; s1[t] = a1;
    __syncthreads();
    for (int st = 128; st > 0; st >>= 1) {
        if (t < st) { s0[t] += s0[t + st]; s1[t] += s1[t + st]; }
        __syncthreads();
    }
    if (t == 0) {
        out[b * Cn + 0] = s0[0] + bh[0];
        out[b * Cn + 1] = s1[0] + bh[1];
    }
}

extern "C" void kernel_launch(void* const* d_in, const int* in_sizes, int n_in,
                              void* d_out, int out_size) {
    (void)in_sizes; (void)n_in; (void)out_size;
    const float* X          = (const float*)d_in[0];
    const float* w_in       = (const float*)d_in[1];
    const float* b_in       = (const float*)d_in[2];
    const float* W          = (const float*)d_in[3];
    const float* bias       = (const float*)d_in[4];
    const float* W_head     = (const float*)d_in[5];
    const float* b_head     = (const float*)d_in[6];
    const int*   gene_map   = (const int*)d_in[7];
    const int*   src        = (const int*)d_in[8];
    const int*   dst_pos    = (const int*)d_in[9];
    const int*   dst_unique = (const int*)d_in[10];
    const int*   root_ids   = (const int*)d_in[11];
    float* out = (float*)d_out;

    int sms = 0;
    cudaDeviceGetAttribute(&sms, cudaDevAttrMultiProcessorCount, 0);

    k_zero_int<<<(Ln * Un + 255) / 256, 256>>>();
    k_alive<<<(Gn + Ln * Un + 255) / 256, 256>>>(gene_map, dst_unique);
    k_gene<<<Gn, 256>>>(X, w_in, b_in, gene_map);

    k_hist<<<(Ln * En + 255) / 256, 256>>>(dst_pos);
    k_scan<<<Ln, 1024>>>();
    k_fill<<<(Ln * En + 255) / 256, 256>>>(dst_pos);

    k_live<<<sms * 8, 128>>>(root_ids, src);               // seed + back x8 + compact (fused)
    k_finish<<<(Ln * Un + 255) / 256, 256>>>(src);         // sort/resolve NEEDED buckets only

    for (int l = 0; l < Ln; l++)
        k_layer<<<dim3(NBLK, 2), 128>>>(l, W, bias, dst_unique + l * Un);

    k_head<<<Bn, 256>>>(W_head, b_head, out);
}

// round 16
// speedup vs baseline: 1.4699x; 1.4699x over previous
#include <cuda_runtime.h>
#include <cuda_fp16.h>
#include <cstdint>

#define Bn 64
#define Nn 50000
#define Ln 8
#define En 100000
#define Un 20000
#define Gn 20000
#define Rn 64
#define Dn 16
#define Cn 2
#define ND (Bn*Dn)     /* 1024 elements per row */
#define NBLK 1024      /* k_layer grid.x */

// Scratch (device globals; zero at module load).
__device__ __half g_h[(size_t)Nn * ND];        // ~102 MB initial node values
__device__ __half g_v[(size_t)Ln * Un * ND];   // ~328 MB version rows [l][u][b][d]
__device__ int    g_csr[Ln * En];              // edge ids -> resolved row ids
__device__ int    g_off[Ln * (Un + 1)];
__device__ int    g_len[Ln * Un];
__device__ int    g_cnt[Ln * Un];
__device__ int    g_cur[Ln * Un];
__device__ int    g_first[Nn];                 // -1 gene, else first dst layer; 127=never
__device__ int    g_mask[Nn];                  // layers where node is a dst
__device__ int    g_inv[Ln * Nn];              // inv[l][node] = u
__device__ int    g_need[Ln * Un];             // backward liveness
__device__ int    g_list[Ln * Un];             // compacted needed u per layer
__device__ int    g_ncnt[Ln];
__device__ int    g_rootrow[Rn];               // absolute row per root

__global__ void k_zero_int() {
    int i = blockIdx.x * blockDim.x + threadIdx.x;
    if (i < Ln * Un) { g_cnt[i] = 0; g_cur[i] = 0; g_need[i] = 0; }
    if (i < Nn) { g_first[i] = 127; g_mask[i] = 0; }
}

__global__ void k_alive(const int* __restrict__ gene_map, const int* __restrict__ dst_unique) {
    int i = blockIdx.x * blockDim.x + threadIdx.x;
    if (i < Gn) {
        atomicMin(&g_first[gene_map[i]], -1);
    } else if (i < Gn + Ln * Un) {
        int k = i - Gn;
        int l = k / Un;
        int u = k - l * Un;
        int node = dst_unique[k];
        atomicMin(&g_first[node], l);
        atomicOr(&g_mask[node], 1 << l);
        g_inv[l * Nn + node] = u;
    }
}

__global__ void k_gene(const float* __restrict__ X, const float* __restrict__ w_in,
                       const float* __restrict__ b_in, const int* __restrict__ gene_map) {
    int g = blockIdx.x;
    int t = threadIdx.x;
    int b = t >> 2, j0 = (t & 3) << 2;
    int node = gene_map[g];
    float x = X[(size_t)b * Gn + g];
    float4 w  = *(const float4*)(w_in + j0);
    float4 bi = *(const float4*)(b_in + j0);
    __half2 h01 = __floats2half2_rn(fmaf(x, w.x, bi.x), fmaf(x, w.y, bi.y));
    __half2 h23 = __floats2half2_rn(fmaf(x, w.z, bi.z), fmaf(x, w.w, bi.w));
    __half2* dst = (__half2*)(g_h + (size_t)node * ND + t * 4);
    dst[0] = h01;
    dst[1] = h23;
}

__global__ void k_hist(const int* __restrict__ dst_pos) {
    int i = blockIdx.x * blockDim.x + threadIdx.x;
    if (i < Ln * En) {
        int l = i / En;
        atomicAdd(&g_cnt[l * Un + dst_pos[i]], 1);
    }
}

__global__ void k_scan() {
    int l = blockIdx.x;
    const int* c = g_cnt + l * Un;
    int* o = g_off + l * (Un + 1);
    int t = threadIdx.x;
    int lane = t & 31, wid = t >> 5;
    int base = t * 20;
    int cnt[20];
    int s = 0;
    #pragma unroll
    for (int i = 0; i < 20; i++) {
        int idx = base + i;
        cnt[i] = (idx < Un) ? c[idx] : 0;
        s += cnt[i];
    }
    int v = s;
    #pragma unroll
    for (int d = 1; d < 32; d <<= 1) {
        int w = __shfl_up_sync(0xffffffffu, v, d);
        if (lane >= d) v += w;
    }
    __shared__ int wsum[32];
    if (lane == 31) wsum[wid] = v;
    __syncthreads();
    if (wid == 0) {
        int wv = wsum[lane];
        #pragma unroll
        for (int d = 1; d < 32; d <<= 1) {
            int w = __shfl_up_sync(0xffffffffu, wv, d);
            if (lane >= d) wv += w;
        }
        wsum[lane] = wv;
    }
    __syncthreads();
    int run = v - s + (wid > 0 ? wsum[wid - 1] : 0);
    #pragma unroll
    for (int i = 0; i < 20; i++) {
        int idx = base + i;
        if (idx < Un) {
            o[idx] = run;
            run += cnt[i];
        }
    }
    if (t == 1023) o[Un] = run;
}

__global__ void k_fill(const int* __restrict__ dst_pos) {
    int i = blockIdx.x * blockDim.x + threadIdx.x;
    if (i < Ln * En) {
        int l = i / En;
        int e = i - l * En;
        int u = dst_pos[i];
        int slot = g_off[l * (Un + 1) + u] + atomicAdd(&g_cur[l * Un + u], 1);
        g_csr[l * En + slot] = e;
    }
}

// Resolve (NO sort): map edge id -> src node -> absolute row id, compact to alive srcs.
// Order within bucket is nondeterministic here; k_finish sorts needed buckets later.
__global__ void k_resolve(const int* __restrict__ src) {
    int gid = blockIdx.x * blockDim.x + threadIdx.x;
    if (gid >= Ln * Un) return;
    int l = gid / Un;
    int u = gid - l * Un;
    int* seg = g_csr + l * En;
    int lo = g_off[l * (Un + 1) + u];
    int hi = g_off[l * (Un + 1) + u + 1];
    const int* sl = src + l * En;
    unsigned below = (1u << l) - 1u;
    int w = lo;
    for (int i = lo; i < hi; i++) {
        int s = sl[seg[i]];
        if (g_first[s] < l) {
            unsigned m = (unsigned)g_mask[s] & below;
            int row;
            if (m) {
                int k = 31 - __clz(m);
                row = Nn + k * Un + g_inv[k * Nn + s];
            } else {
                row = s;
            }
            seg[w++] = row;     // w <= i: safe in-place
        }
    }
    g_len[l * Un + u] = w - lo;
}

// Seed: each root's final version slot is needed; record its absolute row for k_head.
__global__ void k_seed(const int* __restrict__ roots) {
    int r = threadIdx.x;
    if (r >= Rn) return;
    int node = roots[r];
    int m = g_mask[node];
    if (m) {
        int k = 31 - __clz((unsigned)m);
        int u = g_inv[k * Nn + node];
        g_need[k * Un + u] = 1;
        g_rootrow[r] = Nn + k * Un + u;
    } else {
        g_rootrow[r] = node;
    }
}

// Backward: needed slot marks every version row it reads (rows already resolved).
__global__ void k_back(int l) {
    int u = blockIdx.x * blockDim.x + threadIdx.x;
    if (u >= Un) return;
    if (!g_need[l * Un + u]) return;
    int lo = g_off[l * (Un + 1) + u];
    int n = g_len[l * Un + u];
    const int* e = g_csr + l * En + lo;
    for (int i = 0; i < n; i++) {
        int row = e[i];
        if (row >= Nn) g_need[row - Nn] = 1;
    }
}

// Compact needed u's into per-layer lists (u ascending). Block per layer.
__global__ void k_compact() {
    int l = blockIdx.x;
    const int* nd = g_need + l * Un;
    int* lst = g_list + l * Un;
    int t = threadIdx.x;
    int lane = t & 31, wid = t >> 5;
    int base = t * 20;
    int flg[20];
    int s = 0;
    #pragma unroll
    for (int i = 0; i < 20; i++) {
        int idx = base + i;
        flg[i] = (idx < Un) ? nd[idx] : 0;
        s += flg[i];
    }
    int v = s;
    #pragma unroll
    for (int d = 1; d < 32; d <<= 1) {
        int w = __shfl_up_sync(0xffffffffu, v, d);
        if (lane >= d) v += w;
    }
    __shared__ int wsum[32];
    if (lane == 31) wsum[wid] = v;
    __syncthreads();
    if (wid == 0) {
        int wv = wsum[lane];
        #pragma unroll
        for (int d = 1; d < 32; d <<= 1) {
            int w = __shfl_up_sync(0xffffffffu, wv, d);
            if (lane >= d) wv += w;
        }
        wsum[lane] = wv;
    }
    __syncthreads();
    int run = v - s + (wid > 0 ? wsum[wid - 1] : 0);
    #pragma unroll
    for (int i = 0; i < 20; i++) {
        int idx = base + i;
        if (idx < Un && flg[i]) lst[run++] = idx;
    }
    if (t == 1023) g_ncnt[l] = run;
}

// Sort resolved ROW ids for NEEDED buckets only (canonical deterministic sum order;
// duplicate rows are identical values, so equal-key order is irrelevant).
__global__ void k_finish() {
    int gid = blockIdx.x * blockDim.x + threadIdx.x;
    if (gid >= Ln * Un) return;
    if (!g_need[gid]) return;
    int l = gid / Un;
    int u = gid - l * Un;
    int* seg = g_csr + l * En;
    int lo = g_off[l * (Un + 1) + u];
    int hi = lo + g_len[l * Un + u];
    for (int i = lo + 1; i < hi; i++) {
        int key = seg[i];
        int j = i - 1;
        while (j >= lo && seg[j] > key) { seg[j + 1] = seg[j]; j--; }
        seg[j + 1] = key;
    }
}

// Fused layer kernel (round-13 structure, unchanged hot loop).
__global__ __launch_bounds__(128) void k_layer(int l, const float* __restrict__ W,
                                               const float* __restrict__ bias,
                                               const int* __restrict__ dstu) {
    __shared__ float sW[256];
    __shared__ int scnt;
    int t = threadIdx.x;
    if (t == 0) scnt = g_ncnt[l];
    const float* Wl = W + l * Dn * Dn;
    sW[t] = Wl[t];
    sW[t + 128] = Wl[t + 128];
    __syncthreads();
    int cnt = scnt;

    int half = t >> 6;
    int tt = t & 63;
    int kh = tt & 1;
    int k0 = kh << 3;
    size_t col = ((size_t)blockIdx.y << 9) + ((size_t)tt << 3);
    const unsigned long long* sW64 = (const unsigned long long*)sW;

    for (int it = blockIdx.x * 2 + half; it < cnt; it += NBLK * 2) {
        int u = g_list[l * Un + it];
        int lo = g_off[l * (Un + 1) + u];
        int n = g_len[l * Un + u];
        const int* e = g_csr + l * En + lo;

        float a[8] = {0.f, 0.f, 0.f, 0.f, 0.f, 0.f, 0.f, 0.f};
        uint4 p0, p1;
        if (n > 0) {
            int r = e[0];
            const __half* bp = (r < Nn) ? (g_h + (size_t)r * ND) : (g_v + (size_t)(r - Nn) * ND);
            p0 = *(const uint4*)(bp + col);
        }
        if (n > 1) {
            int r = e[1];
            const __half* bp = (r < Nn) ? (g_h + (size_t)r * ND) : (g_v + (size_t)(r - Nn) * ND);
            p1 = *(const uint4*)(bp + col);
        }
        for (int i = 0; i < n; i++) {
            uint4 d = p0;
            p0 = p1;
            if (i + 2 < n) {
                int r = e[i + 2];
                const __half* bp = (r < Nn) ? (g_h + (size_t)r * ND) : (g_v + (size_t)(r - Nn) * ND);
                p1 = *(const uint4*)(bp + col);
            }
            float2 f0 = __half22float2(*(const __half2*)&d.x);
            float2 f1 = __half22float2(*(const __half2*)&d.y);
            float2 f2 = __half22float2(*(const __half2*)&d.z);
            float2 f3 = __half22float2(*(const __half2*)&d.w);
            a[0] += f0.x; a[1] += f0.y; a[2] += f1.x; a[3] += f1.y;
            a[4] += f2.x; a[5] += f2.y; a[6] += f3.x; a[7] += f3.y;
        }

        unsigned long long acc[8];
        #pragma unroll
        for (int jp = 0; jp < 8; jp++) acc[jp] = 0ull;
        #pragma unroll
        for (int kk = 0; kk < 8; kk++) {
            unsigned long long s2;
            asm("mov.b64 %0, {%1, %1};" : "=l"(s2) : "f"(a[kk]));
            int rb = (k0 + kk) << 3;
            #pragma unroll
            for (int jp = 0; jp < 8; jp++) {
                asm("fma.rn.f32x2 %0, %1, %2, %0;" : "+l"(acc[jp]) : "l"(s2), "l"(sW64[rb + jp]));
            }
        }

        int mb = kh << 2, ob = (kh ^ 1) << 2;
        float r[8];
        #pragma unroll
        for (int i = 0; i < 4; i++) {
            unsigned long long mine  = acc[mb + i];
            unsigned long long other = __shfl_xor_sync(0xffffffffu, acc[ob + i], 1);
            float mlo, mhi, olo, ohi;
            asm("mov.b64 {%0, %1}, %2;" : "=f"(mlo), "=f"(mhi) : "l"(mine));
            asm("mov.b64 {%0, %1}, %2;" : "=f"(olo), "=f"(ohi) : "l"(other));
            r[i * 2]     = mlo + olo;
            r[i * 2 + 1] = mhi + ohi;
        }

        int node = dstu[u];
        float4 b0 = *(const float4*)(bias + (size_t)node * Dn + k0);
        float4 b1 = *(const float4*)(bias + (size_t)node * Dn + k0 + 4);
        __half2 o0 = __floats2half2_rn(tanhf(r[0] + b0.x), tanhf(r[1] + b0.y));
        __half2 o1 = __floats2half2_rn(tanhf(r[2] + b0.z), tanhf(r[3] + b0.w));
        __half2 o2 = __floats2half2_rn(tanhf(r[4] + b1.x), tanhf(r[5] + b1.y));
        __half2 o3 = __floats2half2_rn(tanhf(r[6] + b1.z), tanhf(r[7] + b1.w));
        __half2* dst = (__half2*)(g_v + ((size_t)(l * Un + u)) * ND + col);
        dst[0] = o0; dst[1] = o1; dst[2] = o2; dst[3] = o3;
    }
}

__global__ void k_head(const float* __restrict__ Wh, const float* __restrict__ bh,
                       float* __restrict__ out) {
    int b = blockIdx.x;
    int t = threadIdx.x;
    float a0 = 0.f, a1 = 0.f;
    for (int i = t; i < Rn * Dn; i += 256) {
        int r = i >> 4, j = i & 15;
        int row = g_rootrow[r];
        const __half* bp = (row < Nn) ? (g_h + (size_t)row * ND) : (g_v + (size_t)(row - Nn) * ND);
        float f = __half2float(bp[(b << 4) + j]);
        a0 = fmaf(f, Wh[i], a0);
        a1 = fmaf(f, Wh[Rn * Dn + i], a1);
    }
    __shared__ float s0[256], s1[256];
    s0[t] = a0; s1[t] = a1;
    __syncthreads();
    for (int st = 128; st > 0; st >>= 1) {
        if (t < st) { s0[t] += s0[t + st]; s1[t] += s1[t + st]; }
        __syncthreads();
    }
    if (t == 0) {
        out[b * Cn + 0] = s0[0] + bh[0];
        out[b * Cn + 1] = s1[0] + bh[1];
    }
}

extern "C" void kernel_launch(void* const* d_in, const int* in_sizes, int n_in,
                              void* d_out, int out_size) {
    (void)in_sizes; (void)n_in; (void)out_size;
    const float* X          = (const float*)d_in[0];
    const float* w_in       = (const float*)d_in[1];
    const float* b_in       = (const float*)d_in[2];
    const float* W          = (const float*)d_in[3];
    const float* bias       = (const float*)d_in[4];
    const float* W_head     = (const float*)d_in[5];
    const float* b_head     = (const float*)d_in[6];
    const int*   gene_map   = (const int*)d_in[7];
    const int*   src        = (const int*)d_in[8];
    const int*   dst_pos    = (const int*)d_in[9];
    const int*   dst_unique = (const int*)d_in[10];
    const int*   root_ids   = (const int*)d_in[11];
    float* out = (float*)d_out;

    k_zero_int<<<(Ln * Un + 255) / 256, 256>>>();
    k_alive<<<(Gn + Ln * Un + 255) / 256, 256>>>(gene_map, dst_unique);
    k_gene<<<Gn, 256>>>(X, w_in, b_in, gene_map);

    // CSR build (all layers batched)
    k_hist<<<(Ln * En + 255) / 256, 256>>>(dst_pos);
    k_scan<<<Ln, 1024>>>();
    k_fill<<<(Ln * En + 255) / 256, 256>>>(dst_pos);
    k_resolve<<<(Ln * Un + 255) / 256, 256>>>(src);    // map + compact, NO sort

    // Backward liveness + work-list compaction
    k_seed<<<1, 64>>>(root_ids);
    for (int l = Ln - 1; l >= 0; l--)
        k_back<<<(Un + 255) / 256, 256>>>(l);
    k_compact<<<Ln, 1024>>>();
    k_finish<<<(Ln * Un + 255) / 256, 256>>>();        // sort needed buckets only

    // One fused kernel per layer over compacted work lists
    for (int l = 0; l < Ln; l++)
        k_layer<<<dim3(NBLK, 2), 128>>>(l, W, bias, dst_unique + l * Un);

    k_head<<<Bn, 256>>>(W_head, b_head, out);
}

// round 17
// speedup vs baseline: 1.5208x; 1.0346x over previous
#include <cuda_runtime.h>
#include <cuda_fp16.h>
#include <cstdint>

#define Bn 64
#define Nn 50000
#define Ln 8
#define En 100000
#define Un 20000
#define Gn 20000
#define Rn 64
#define Dn 16
#define Cn 2
#define ND (Bn*Dn)     /* 1024 elements per row */
#define NBLK 1024      /* k_layer grid.x */

// Scratch (device globals; zero at module load).
__device__ __half g_h[(size_t)Nn * ND];        // ~102 MB initial node values
__device__ __half g_v[(size_t)Ln * Un * ND];   // ~328 MB version rows [l][u][b][d]
__device__ int    g_csr[Ln * En];              // edge ids -> resolved row ids
__device__ int    g_off[Ln * (Un + 1)];
__device__ int    g_len[Ln * Un];
__device__ int    g_cnt[Ln * Un];
__device__ int    g_cur[Ln * Un];
__device__ int    g_first[Nn];
__device__ int    g_mask[Nn];
__device__ int    g_inv[Ln * Nn];
__device__ int    g_need[Ln * Un];
__device__ int    g_list[Ln * Un];
__device__ int    g_ncnt[Ln];
__device__ int    g_rootrow[Rn];

__global__ void k_zero_int() {
    int i = blockIdx.x * blockDim.x + threadIdx.x;
    if (i < Ln * Un) { g_cnt[i] = 0; g_cur[i] = 0; g_need[i] = 0; }
    if (i < Nn) { g_first[i] = 127; g_mask[i] = 0; }
}

__global__ void k_alive(const int* __restrict__ gene_map, const int* __restrict__ dst_unique) {
    int i = blockIdx.x * blockDim.x + threadIdx.x;
    if (i < Gn) {
        atomicMin(&g_first[gene_map[i]], -1);
    } else if (i < Gn + Ln * Un) {
        int k = i - Gn;
        int l = k / Un;
        int u = k - l * Un;
        int node = dst_unique[k];
        atomicMin(&g_first[node], l);
        atomicOr(&g_mask[node], 1 << l);
        g_inv[l * Nn + node] = u;
    }
}

__global__ void k_gene(const float* __restrict__ X, const float* __restrict__ w_in,
                       const float* __restrict__ b_in, const int* __restrict__ gene_map) {
    int g = blockIdx.x;
    int t = threadIdx.x;
    int b = t >> 2, j0 = (t & 3) << 2;
    int node = gene_map[g];
    float x = X[(size_t)b * Gn + g];
    float4 w  = *(const float4*)(w_in + j0);
    float4 bi = *(const float4*)(b_in + j0);
    __half2 h01 = __floats2half2_rn(fmaf(x, w.x, bi.x), fmaf(x, w.y, bi.y));
    __half2 h23 = __floats2half2_rn(fmaf(x, w.z, bi.z), fmaf(x, w.w, bi.w));
    __half2* dst = (__half2*)(g_h + (size_t)node * ND + t * 4);
    dst[0] = h01;
    dst[1] = h23;
}

__global__ void k_hist(const int* __restrict__ dst_pos) {
    int i = blockIdx.x * blockDim.x + threadIdx.x;
    if (i < Ln * En) {
        int l = i / En;
        atomicAdd(&g_cnt[l * Un + dst_pos[i]], 1);
    }
}

__global__ void k_scan() {
    int l = blockIdx.x;
    const int* c = g_cnt + l * Un;
    int* o = g_off + l * (Un + 1);
    int t = threadIdx.x;
    int lane = t & 31, wid = t >> 5;
    int base = t * 20;
    int cnt[20];
    int s = 0;
    #pragma unroll
    for (int i = 0; i < 20; i++) {
        int idx = base + i;
        cnt[i] = (idx < Un) ? c[idx] : 0;
        s += cnt[i];
    }
    int v = s;
    #pragma unroll
    for (int d = 1; d < 32; d <<= 1) {
        int w = __shfl_up_sync(0xffffffffu, v, d);
        if (lane >= d) v += w;
    }
    __shared__ int wsum[32];
    if (lane == 31) wsum[wid] = v;
    __syncthreads();
    if (wid == 0) {
        int wv = wsum[lane];
        #pragma unroll
        for (int d = 1; d < 32; d <<= 1) {
            int w = __shfl_up_sync(0xffffffffu, wv, d);
            if (lane >= d) wv += w;
        }
        wsum[lane] = wv;
    }
    __syncthreads();
    int run = v - s + (wid > 0 ? wsum[wid - 1] : 0);
    #pragma unroll
    for (int i = 0; i < 20; i++) {
        int idx = base + i;
        if (idx < Un) {
            o[idx] = run;
            run += cnt[i];
        }
    }
    if (t == 1023) o[Un] = run;
}

__global__ void k_fill(const int* __restrict__ dst_pos) {
    int i = blockIdx.x * blockDim.x + threadIdx.x;
    if (i < Ln * En) {
        int l = i / En;
        int e = i - l * En;
        int u = dst_pos[i];
        int slot = g_off[l * (Un + 1) + u] + atomicAdd(&g_cur[l * Un + u], 1);
        g_csr[l * En + slot] = e;
    }
}

// Resolve (NO sort): map edge id -> src node -> absolute row id, compact to alive srcs.
__global__ void k_resolve(const int* __restrict__ src) {
    int gid = blockIdx.x * blockDim.x + threadIdx.x;
    if (gid >= Ln * Un) return;
    int l = gid / Un;
    int u = gid - l * Un;
    int* seg = g_csr + l * En;
    int lo = g_off[l * (Un + 1) + u];
    int hi = g_off[l * (Un + 1) + u + 1];
    const int* sl = src + l * En;
    unsigned below = (1u << l) - 1u;
    int w = lo;
    for (int i = lo; i < hi; i++) {
        int s = sl[seg[i]];
        if (g_first[s] < l) {
            unsigned m = (unsigned)g_mask[s] & below;
            int row;
            if (m) {
                int k = 31 - __clz(m);
                row = Nn + k * Un + g_inv[k * Nn + s];
            } else {
                row = s;
            }
            seg[w++] = row;
        }
    }
    g_len[l * Un + u] = w - lo;
}

__global__ void k_seed(const int* __restrict__ roots) {
    int r = threadIdx.x;
    if (r >= Rn) return;
    int node = roots[r];
    int m = g_mask[node];
    if (m) {
        int k = 31 - __clz((unsigned)m);
        int u = g_inv[k * Nn + node];
        g_need[k * Un + u] = 1;
        g_rootrow[r] = Nn + k * Un + u;
    } else {
        g_rootrow[r] = node;
    }
}

__global__ void k_back(int l) {
    int u = blockIdx.x * blockDim.x + threadIdx.x;
    if (u >= Un) return;
    if (!g_need[l * Un + u]) return;
    int lo = g_off[l * (Un + 1) + u];
    int n = g_len[l * Un + u];
    const int* e = g_csr + l * En + lo;
    for (int i = 0; i < n; i++) {
        int row = e[i];
        if (row >= Nn) g_need[row - Nn] = 1;
    }
}

__global__ void k_compact() {
    int l = blockIdx.x;
    const int* nd = g_need + l * Un;
    int* lst = g_list + l * Un;
    int t = threadIdx.x;
    int lane = t & 31, wid = t >> 5;
    int base = t * 20;
    int flg[20];
    int s = 0;
    #pragma unroll
    for (int i = 0; i < 20; i++) {
        int idx = base + i;
        flg[i] = (idx < Un) ? nd[idx] : 0;
        s += flg[i];
    }
    int v = s;
    #pragma unroll
    for (int d = 1; d < 32; d <<= 1) {
        int w = __shfl_up_sync(0xffffffffu, v, d);
        if (lane >= d) v += w;
    }
    __shared__ int wsum[32];
    if (lane == 31) wsum[wid] = v;
    __syncthreads();
    if (wid == 0) {
        int wv = wsum[lane];
        #pragma unroll
        for (int d = 1; d < 32; d <<= 1) {
            int w = __shfl_up_sync(0xffffffffu, wv, d);
            if (lane >= d) wv += w;
        }
        wsum[lane] = wv;
    }
    __syncthreads();
    int run = v - s + (wid > 0 ? wsum[wid - 1] : 0);
    #pragma unroll
    for (int i = 0; i < 20; i++) {
        int idx = base + i;
        if (idx < Un && flg[i]) lst[run++] = idx;
    }
    if (t == 1023) g_ncnt[l] = run;
}

// Sort resolved row ids for NEEDED buckets only.
__global__ void k_finish() {
    int gid = blockIdx.x * blockDim.x + threadIdx.x;
    if (gid >= Ln * Un) return;
    if (!g_need[gid]) return;
    int l = gid / Un;
    int u = gid - l * Un;
    int n = g_len[l * Un + u];
    if (n <= 1) return;
    int* seg = g_csr + l * En;
    int lo = g_off[l * (Un + 1) + u];
    int hi = lo + n;
    for (int i = lo + 1; i < hi; i++) {
        int key = seg[i];
        int j = i - 1;
        while (j >= lo && seg[j] > key) { seg[j + 1] = seg[j]; j--; }
        seg[j + 1] = key;
    }
}

// Fused layer kernel (unchanged hot loop).
__global__ __launch_bounds__(128) void k_layer(int l, const float* __restrict__ W,
                                               const float* __restrict__ bias,
                                               const int* __restrict__ dstu) {
    __shared__ float sW[256];
    __shared__ int scnt;
    int t = threadIdx.x;
    if (t == 0) scnt = g_ncnt[l];
    const float* Wl = W + l * Dn * Dn;
    sW[t] = Wl[t];
    sW[t + 128] = Wl[t + 128];
    __syncthreads();
    int cnt = scnt;

    int half = t >> 6;
    int tt = t & 63;
    int kh = tt & 1;
    int k0 = kh << 3;
    size_t col = ((size_t)blockIdx.y << 9) + ((size_t)tt << 3);
    const unsigned long long* sW64 = (const unsigned long long*)sW;

    for (int it = blockIdx.x * 2 + half; it < cnt; it += NBLK * 2) {
        int u = g_list[l * Un + it];
        int lo = g_off[l * (Un + 1) + u];
        int n = g_len[l * Un + u];
        const int* e = g_csr + l * En + lo;

        float a[8] = {0.f, 0.f, 0.f, 0.f, 0.f, 0.f, 0.f, 0.f};
        uint4 p0, p1;
        if (n > 0) {
            int r = e[0];
            const __half* bp = (r < Nn) ? (g_h + (size_t)r * ND) : (g_v + (size_t)(r - Nn) * ND);
            p0 = *(const uint4*)(bp + col);
        }
        if (n > 1) {
            int r = e[1];
            const __half* bp = (r < Nn) ? (g_h + (size_t)r * ND) : (g_v + (size_t)(r - Nn) * ND);
            p1 = *(const uint4*)(bp + col);
        }
        for (int i = 0; i < n; i++) {
            uint4 d = p0;
            p0 = p1;
            if (i + 2 < n) {
                int r = e[i + 2];
                const __half* bp = (r < Nn) ? (g_h + (size_t)r * ND) : (g_v + (size_t)(r - Nn) * ND);
                p1 = *(const uint4*)(bp + col);
            }
            float2 f0 = __half22float2(*(const __half2*)&d.x);
            float2 f1 = __half22float2(*(const __half2*)&d.y);
            float2 f2 = __half22float2(*(const __half2*)&d.z);
            float2 f3 = __half22float2(*(const __half2*)&d.w);
            a[0] += f0.x; a[1] += f0.y; a[2] += f1.x; a[3] += f1.y;
            a[4] += f2.x; a[5] += f2.y; a[6] += f3.x; a[7] += f3.y;
        }

        unsigned long long acc[8];
        #pragma unroll
        for (int jp = 0; jp < 8; jp++) acc[jp] = 0ull;
        #pragma unroll
        for (int kk = 0; kk < 8; kk++) {
            unsigned long long s2;
            asm("mov.b64 %0, {%1, %1};" : "=l"(s2) : "f"(a[kk]));
            int rb = (k0 + kk) << 3;
            #pragma unroll
            for (int jp = 0; jp < 8; jp++) {
                asm("fma.rn.f32x2 %0, %1, %2, %0;" : "+l"(acc[jp]) : "l"(s2), "l"(sW64[rb + jp]));
            }
        }

        int mb = kh << 2, ob = (kh ^ 1) << 2;
        float r[8];
        #pragma unroll
        for (int i = 0; i < 4; i++) {
            unsigned long long mine  = acc[mb + i];
            unsigned long long other = __shfl_xor_sync(0xffffffffu, acc[ob + i], 1);
            float mlo, mhi, olo, ohi;
            asm("mov.b64 {%0, %1}, %2;" : "=f"(mlo), "=f"(mhi) : "l"(mine));
            asm("mov.b64 {%0, %1}, %2;" : "=f"(olo), "=f"(ohi) : "l"(other));
            r[i * 2]     = mlo + olo;
            r[i * 2 + 1] = mhi + ohi;
        }

        int node = dstu[u];
        float4 b0 = *(const float4*)(bias + (size_t)node * Dn + k0);
        float4 b1 = *(const float4*)(bias + (size_t)node * Dn + k0 + 4);
        __half2 o0 = __floats2half2_rn(tanhf(r[0] + b0.x), tanhf(r[1] + b0.y));
        __half2 o1 = __floats2half2_rn(tanhf(r[2] + b0.z), tanhf(r[3] + b0.w));
        __half2 o2 = __floats2half2_rn(tanhf(r[4] + b1.x), tanhf(r[5] + b1.y));
        __half2 o3 = __floats2half2_rn(tanhf(r[6] + b1.z), tanhf(r[7] + b1.w));
        __half2* dst = (__half2*)(g_v + ((size_t)(l * Un + u)) * ND + col);
        dst[0] = o0; dst[1] = o1; dst[2] = o2; dst[3] = o3;
    }
}

__global__ void k_head(const float* __restrict__ Wh, const float* __restrict__ bh,
                       float* __restrict__ out) {
    int b = blockIdx.x;
    int t = threadIdx.x;
    float a0 = 0.f, a1 = 0.f;
    for (int i = t; i < Rn * Dn; i += 256) {
        int r = i >> 4, j = i & 15;
        int row = g_rootrow[r];
        const __half* bp = (row < Nn) ? (g_h + (size_t)row * ND) : (g_v + (size_t)(row - Nn) * ND);
        float f = __half2float(bp[(b << 4) + j]);
        a0 = fmaf(f, Wh[i], a0);
        a1 = fmaf(f, Wh[Rn * Dn + i], a1);
    }
    __shared__ float s0[256], s1[256];
    s0[t] = a0; s1[t] = a1;
    __syncthreads();
    for (int st = 128; st > 0; st >>= 1) {
        if (t < st) { s0[t] += s0[t + st]; s1[t] += s1[t + st]; }
        __syncthreads();
    }
    if (t == 0) {
        out[b * Cn + 0] = s0[0] + bh[0];
        out[b * Cn + 1] = s1[0] + bh[1];
    }
}

extern "C" void kernel_launch(void* const* d_in, const int* in_sizes, int n_in,
                              void* d_out, int out_size) {
    (void)in_sizes; (void)n_in; (void)out_size;
    const float* X          = (const float*)d_in[0];
    const float* w_in       = (const float*)d_in[1];
    const float* b_in       = (const float*)d_in[2];
    const float* W          = (const float*)d_in[3];
    const float* bias       = (const float*)d_in[4];
    const float* W_head     = (const float*)d_in[5];
    const float* b_head     = (const float*)d_in[6];
    const int*   gene_map   = (const int*)d_in[7];
    const int*   src        = (const int*)d_in[8];
    const int*   dst_pos    = (const int*)d_in[9];
    const int*   dst_unique = (const int*)d_in[10];
    const int*   root_ids   = (const int*)d_in[11];
    float* out = (float*)d_out;

    // Side streams + events for fork-join graph parallelism (created once; host-side
    // handles only, no device memory).
    static cudaStream_t sA = 0, sB = 0;
    static cudaEvent_t eFork = 0, eGene = 0, eZero = 0, eSeed = 0, eBack = 0, eComp = 0;
    if (sA == 0) {
        cudaStreamCreateWithFlags(&sA, cudaStreamNonBlocking);
        cudaStreamCreateWithFlags(&sB, cudaStreamNonBlocking);
        cudaEventCreateWithFlags(&eFork, cudaEventDisableTiming);
        cudaEventCreateWithFlags(&eGene, cudaEventDisableTiming);
        cudaEventCreateWithFlags(&eZero, cudaEventDisableTiming);
        cudaEventCreateWithFlags(&eSeed, cudaEventDisableTiming);
        cudaEventCreateWithFlags(&eBack, cudaEventDisableTiming);
        cudaEventCreateWithFlags(&eComp, cudaEventDisableTiming);
    }

    // Fork: gene embedding runs on sB, fully parallel to the CSR/liveness build.
    cudaEventRecord(eFork, 0);
    cudaStreamWaitEvent(sB, eFork, 0);
    k_gene<<<Gn, 256, 0, sB>>>(X, w_in, b_in, gene_map);
    cudaEventRecord(eGene, sB);

    // Main chain: zero, then fork alive+seed to sA in parallel with hist/scan/fill.
    k_zero_int<<<(Ln * Un + 255) / 256, 256>>>();
    cudaEventRecord(eZero, 0);
    cudaStreamWaitEvent(sA, eZero, 0);
    k_alive<<<(Gn + Ln * Un + 255) / 256, 256, 0, sA>>>(gene_map, dst_unique);
    k_seed<<<1, 64, 0, sA>>>(root_ids);
    cudaEventRecord(eSeed, sA);

    k_hist<<<(Ln * En + 255) / 256, 256>>>(dst_pos);
    k_scan<<<Ln, 1024>>>();
    k_fill<<<(Ln * En + 255) / 256, 256>>>(dst_pos);

    // Join alive/seed before resolve (needs g_first/g_mask/g_inv).
    cudaStreamWaitEvent(0, eSeed, 0);
    k_resolve<<<(Ln * Un + 255) / 256, 256>>>(src);

    for (int l = Ln - 1; l >= 0; l--)
        k_back<<<(Un + 255) / 256, 256>>>(l);
    cudaEventRecord(eBack, 0);

    // compact (sA) overlaps finish (main).
    cudaStreamWaitEvent(sA, eBack, 0);
    k_compact<<<Ln, 1024, 0, sA>>>();
    cudaEventRecord(eComp, sA);

    k_finish<<<(Ln * Un + 255) / 256, 256>>>();

    // Join compact + gene before the layer chain.
    cudaStreamWaitEvent(0, eComp, 0);
    cudaStreamWaitEvent(0, eGene, 0);

    for (int l = 0; l < Ln; l++)
        k_layer<<<dim3(NBLK, 2), 128>>>(l, W, bias, dst_unique + l * Un);

    k_head<<<Bn, 256>>>(W_head, b_head, out);
}